// round 11
// baseline (speedup 1.0000x reference)
#include <cuda_runtime.h>
#include <cuda_bf16.h>

// NeRF deterministic inverse-CDF sampling — TWO rays per warp.
// Lanes 0-15 = ray A, lanes 16-31 = ray B; all shuffles width=16.
// Per half-warp: lane hl owns bins 8hl..8hl+7 and samples 8hl..8hl+7.
//  1. warp-cooperative coalesced weight load (dense 128B rows, both rays)
//     -> smem transpose -> 8 lane-minor weights per lane (2x LDS.128)
//  2. 7 serial adds + width-16 warp scan (4 steps); exact sample boundaries
//     via identical fmaf on identical values (exact partition of [0,128));
//     chained-min guard for the cross-tree fp hazard; __float2int_ru.
//  3. normalized CDF stored densely (2x STS.128 per lane)
//  4. owner ids byte-packed: STS.64 init (hoisted), STS.8 at bin starts,
//     LDS.64 readback, width-16 inclusive MAX-scan (segment-id fill)
//  5. per-sample lo=cdf[i], hi=cdf[i+1], t=(u-lo)*rcp(hi-lo); 2x STG.128.
// All warp-uniform work (intersection/scan/rcp/sync) amortized over 2 rays.

#define WPB 8
#define FULL 0xffffffffu

__global__ __launch_bounds__(WPB * 32)
void nerf_sample_kernel(const float* __restrict__ rays_o,
                        const float* __restrict__ rays_d,
                        const float* __restrict__ weights,
                        float* __restrict__ out,
                        int R)
{
    __shared__ __align__(16) float s_w[WPB][2][128];    // transpose buffers
    __shared__ __align__(16) float s_cdf[WPB][2][132];  // 129 used
    __shared__ __align__(16) int   s_own[WPB][2][32];   // 128 owner bytes each

    const int warp = threadIdx.x >> 5;
    const int lane = threadIdx.x & 31;
    const int half = lane >> 4;          // 0: ray A, 1: ray B
    const int hl   = lane & 15;          // lane within half
    const int rayA = (blockIdx.x * WPB + warp) * 2;
    const int ray  = rayA + half;
    if (ray >= R) return;

    float* wbufA  = s_w[warp][0];
    float* wbufB  = s_w[warp][1];
    float* cdfrow = s_cdf[warp][half];
    int*   ownrow = s_own[warp][half];

    // ---- owner-byte init (independent; covered by first syncwarp) ----
    *reinterpret_cast<int2*>(ownrow + 2 * hl) = make_int2(0, 0);

    // ---- near/far cube intersection; 16-lane redundant per ray ----
    const float* o3 = rays_o + 3 * ray;
    const float* d3 = rays_d + 3 * ray;
    float nearv = -1e30f, farv = 1e30f;
#pragma unroll
    for (int a = 0; a < 3; ++a) {
        float oo  = __ldg(o3 + a);
        float dd  = __ldg(d3 + a) + 1e-15f;
        float inv = __fdividef(1.0f, dd);
        float oi  = oo * inv;
        float t0  = -inv - oi;
        float t1  =  inv - oi;
        nearv = fmaxf(nearv, fminf(t0, t1));
        farv  = fminf(farv,  fmaxf(t0, t1));
    }
    nearv = fmaxf(nearv, 0.05f);
    const float sstep = (farv - nearv) * (1.0f / 127.0f);

    // ---- warp-cooperative coalesced weight load for BOTH rays (+eps) ----
    {
        const float* wrA = weights + (long long)rayA * 127;
        const float* wrB = wrA + 127;
#pragma unroll
        for (int k = 0; k < 3; ++k) {
            wbufA[lane + 32 * k] = __ldg(wrA + lane + 32 * k) + 1e-5f;
            wbufB[lane + 32 * k] = __ldg(wrB + lane + 32 * k) + 1e-5f;
        }
        wbufA[lane + 96] = (lane < 31) ? (__ldg(wrA + lane + 96) + 1e-5f) : 0.0f;
        wbufB[lane + 96] = (lane < 31) ? (__ldg(wrB + lane + 96) + 1e-5f) : 0.0f;
    }
    __syncwarp();

    // ---- 8 lane-minor weights, local prefix, width-16 scan ----
    const float* myw = s_w[warp][half] + 8 * hl;
    float4 wa = *reinterpret_cast<const float4*>(myw);
    float4 wb = *reinterpret_cast<const float4*>(myw + 4);

    const float s1 = wa.x;
    const float s2 = s1 + wa.y;
    const float s3 = s2 + wa.z;
    const float s4 = s3 + wa.w;
    const float s5 = s4 + wb.x;
    const float s6 = s5 + wb.y;
    const float s7 = s6 + wb.z;
    const float s8 = s7 + wb.w;

    float incl = s8;
#pragma unroll
    for (int d = 1; d < 16; d <<= 1) {
        float y = __shfl_up_sync(FULL, incl, d, 16);
        if (hl >= d) incl += y;
    }
    float P = __shfl_up_sync(FULL, incl, 1, 16);
    if (hl == 0) P = 0.0f;
    const float total = __shfl_sync(FULL, incl, 15, 16);
    const float rtot  = __fdividef(1.0f, total);
    const float g     = rtot * 128.0f;     // identical within each half

    const float m1 = P + s1, m2 = P + s2, m3 = P + s3, m4 = P + s4;
    const float m5 = P + s5, m6 = P + s6, m7 = P + s7;

    // sample-index boundaries; jb8(hl) == jb0(hl+1) exactly
    int jb0 = __float2int_ru(fmaf(P,    g, -0.5f));
    int jb1 = __float2int_ru(fmaf(m1,   g, -0.5f));
    int jb2 = __float2int_ru(fmaf(m2,   g, -0.5f));
    int jb3 = __float2int_ru(fmaf(m3,   g, -0.5f));
    int jb4 = __float2int_ru(fmaf(m4,   g, -0.5f));
    int jb5 = __float2int_ru(fmaf(m5,   g, -0.5f));
    int jb6 = __float2int_ru(fmaf(m6,   g, -0.5f));
    int jb7 = __float2int_ru(fmaf(m7,   g, -0.5f));
    int jb8 = __float2int_ru(fmaf(incl, g, -0.5f));
    jb7 = min(jb7, jb8);  jb6 = min(jb6, jb7);  jb5 = min(jb5, jb6);
    jb4 = min(jb4, jb5);  jb3 = min(jb3, jb4);  jb2 = min(jb2, jb3);
    jb1 = min(jb1, jb2);

    // ---- store normalized CDF densely ----
    {
        float4 cA, cB;
        cA.x = P  * rtot;  cA.y = m1 * rtot;  cA.z = m2 * rtot;  cA.w = m3 * rtot;
        cB.x = m4 * rtot;  cB.y = m5 * rtot;  cB.z = m6 * rtot;  cB.w = m7 * rtot;
        *reinterpret_cast<float4*>(cdfrow + 8 * hl)     = cA;
        *reinterpret_cast<float4*>(cdfrow + 8 * hl + 4) = cB;
        if (hl == 15) cdfrow[128] = incl * rtot;   // ~1
    }

    // ---- scatter bin id (byte) at each nonempty bin's start ----
    {
        char* ownb = reinterpret_cast<char*>(ownrow);
        const int b = 8 * hl;
        if (jb0 < jb1) ownb[jb0] = (char)(b);
        if (jb1 < jb2) ownb[jb1] = (char)(b + 1);
        if (jb2 < jb3) ownb[jb2] = (char)(b + 2);
        if (jb3 < jb4) ownb[jb3] = (char)(b + 3);
        if (jb4 < jb5) ownb[jb4] = (char)(b + 4);
        if (jb5 < jb6) ownb[jb5] = (char)(b + 5);
        if (jb6 < jb7) ownb[jb6] = (char)(b + 6);
        if (jb7 < jb8) ownb[jb7] = (char)(b + 7);
    }
    __syncwarp();

    // ---- owner recovery: byte extract + width-16 inclusive MAX-scan ----
    int2 ow = *reinterpret_cast<const int2*>(ownrow + 2 * hl);
    int q0 = ow.x & 0xff;
    int q1 = max(q0, (ow.x >> 8)  & 0xff);
    int q2 = max(q1, (ow.x >> 16) & 0xff);
    int q3 = max(q2, (ow.x >> 24) & 0xff);
    int q4 = max(q3,  ow.y        & 0xff);
    int q5 = max(q4, (ow.y >> 8)  & 0xff);
    int q6 = max(q5, (ow.y >> 16) & 0xff);
    int q7 = max(q6, (ow.y >> 24) & 0xff);

    int v = q7;
#pragma unroll
    for (int d = 1; d < 16; d <<= 1) {
        int y = __shfl_up_sync(FULL, v, d, 16);
        if (hl >= d) v = max(v, y);
    }
    int ex = __shfl_up_sync(FULL, v, 1, 16);
    if (hl == 0) ex = 0;
    const int i0 = max(ex, q0), i1 = max(ex, q1), i2 = max(ex, q2), i3 = max(ex, q3);
    const int i4 = max(ex, q4), i5 = max(ex, q5), i6 = max(ex, q6), i7 = max(ex, q7);

    // ---- per-sample interpolation, 2x STG.128 ----
    const float u0 = fmaf((float)(8 * hl), 0.0078125f, 0.00390625f);
    float* orow = out + (long long)ray * 128 + 8 * hl;

    float4 r1, r2;
#define SAMP(DST, I, KC)  do {                                              \
        float lo = cdfrow[(I)], hi = cdfrow[(I) + 1];                       \
        float den = hi - lo;                                                \
        float rd  = (den < 1e-5f) ? 1.0f : __fdividef(1.0f, den);           \
        float t   = ((u0 + (KC)) - lo) * rd;                                \
        DST = fmaf(sstep, (float)(I) + t, nearv);                           \
    } while (0)
    SAMP(r1.x, i0, 0.0f);
    SAMP(r1.y, i1, 0.0078125f);
    SAMP(r1.z, i2, 0.015625f);
    SAMP(r1.w, i3, 0.0234375f);
    SAMP(r2.x, i4, 0.03125f);
    SAMP(r2.y, i5, 0.0390625f);
    SAMP(r2.z, i6, 0.046875f);
    SAMP(r2.w, i7, 0.0546875f);
#undef SAMP
    *reinterpret_cast<float4*>(orow)     = r1;
    *reinterpret_cast<float4*>(orow + 4) = r2;
}

extern "C" void kernel_launch(void* const* d_in, const int* in_sizes, int n_in,
                              void* d_out, int out_size) {
    const float* rays_o  = (const float*)d_in[0];
    const float* rays_d  = (const float*)d_in[1];
    const float* weights = (const float*)d_in[2];
    float* out = (float*)d_out;

    const int R = in_sizes[0] / 3;   // 262144
    const int pairs = (R + 1) / 2;
    dim3 block(WPB * 32);
    dim3 grid((pairs + WPB - 1) / WPB);
    nerf_sample_kernel<<<grid, block>>>(rays_o, rays_d, weights, out, R);
}